// round 6
// baseline (speedup 1.0000x reference)
#include <cuda_runtime.h>
#include <cooperative_groups.h>
#include <math.h>

namespace cg = cooperative_groups;

// Problem constants
#define SEQ   1024
#define TB    64
#define EMBD  512
#define H0    1024
#define H1    512
#define H2    256
#define OUTD  7
#define G0    (4*H0)
#define NTICK (SEQ + 2)

// One warp per LSTM hidden element: 1024 + 512 + 256 = 1792 warps
// = 112 CTAs x 16 warps. Cooperative launch guarantees co-residency.
#define TICK_CTAS 112

// Scratch (static device arrays — no runtime allocation).
// h histories: slot (t+1) holds h(t); slot 0 holds the zero initial state
// and is NEVER written -> stays zero across graph replays. Every other slot
// is (re)written before it is read on every replay. No reset kernel needed.
__device__ __align__(16) float g_xg0[SEQ * G0];          // 16 MB: Wih0@x + bih0 + bhh0
__device__ __align__(16) float g_h0h[(SEQ + 1) * H0];
__device__ __align__(16) float g_h1h[(SEQ + 1) * H1];
__device__ __align__(16) float g_h2h[(SEQ + 1) * H2];

__device__ __forceinline__ float sigf(float x) { return 1.0f / (1.0f + expf(-x)); }

// ---------------------------------------------------------------------------
// Kernel 1: XG0[t][r] = sum_e emb[tok[t]][e] * Wih0[r][e] + bih0[r] + bhh0[r]
// 64x64 tile GEMM, fused embedding gather (only batch element 63 is live).
// ---------------------------------------------------------------------------
__global__ void xgemm_kernel(const int* __restrict__ tokens,
                             const float* __restrict__ emb,
                             const float* __restrict__ Wih0,
                             const float* __restrict__ bih0,
                             const float* __restrict__ bhh0) {
    __shared__ float As[64][33];
    __shared__ float Bs[64][33];
    __shared__ int toks[64];
    const int t0 = blockIdx.y * 64;
    const int r0 = blockIdx.x * 64;
    const int tid = threadIdx.x;
    if (tid < 64) toks[tid] = tokens[(t0 + tid) * TB + (TB - 1)];
    __syncthreads();

    float acc[4][4] = {};
    const int ty = tid >> 4, tx = tid & 15;

    for (int k0 = 0; k0 < EMBD; k0 += 32) {
#pragma unroll
        for (int l = 0; l < 2; l++) {
            int f4 = tid + l * 256;
            int row = f4 >> 3;
            int c4 = f4 & 7;
            float4 a = *(const float4*)(emb + (size_t)toks[row] * EMBD + k0 + c4 * 4);
            As[row][c4 * 4 + 0] = a.x; As[row][c4 * 4 + 1] = a.y;
            As[row][c4 * 4 + 2] = a.z; As[row][c4 * 4 + 3] = a.w;
            float4 b = *(const float4*)(Wih0 + (size_t)(r0 + row) * EMBD + k0 + c4 * 4);
            Bs[row][c4 * 4 + 0] = b.x; Bs[row][c4 * 4 + 1] = b.y;
            Bs[row][c4 * 4 + 2] = b.z; Bs[row][c4 * 4 + 3] = b.w;
        }
        __syncthreads();
#pragma unroll
        for (int kk = 0; kk < 32; kk++) {
            float a[4], b[4];
#pragma unroll
            for (int i = 0; i < 4; i++) a[i] = As[ty * 4 + i][kk];
#pragma unroll
            for (int j = 0; j < 4; j++) b[j] = Bs[tx * 4 + j][kk];
#pragma unroll
            for (int i = 0; i < 4; i++)
#pragma unroll
                for (int j = 0; j < 4; j++) acc[i][j] += a[i] * b[j];
        }
        __syncthreads();
    }
#pragma unroll
    for (int i = 0; i < 4; i++) {
#pragma unroll
        for (int j = 0; j < 4; j++) {
            int r = r0 + tx * 4 + j;
            int t = t0 + ty * 4 + i;
            g_xg0[(size_t)t * G0 + r] = acc[i][j] + bih0[r] + bhh0[r];
        }
    }
}

// ---------------------------------------------------------------------------
// Kernel 2: cooperative pipelined recurrence. grid.sync() is the tick barrier.
// Tick k: L0 computes t=k, L1 t=k-1, L2 t=k-2. One warp per hidden element;
// weights streamed from global (L2-resident, ~26MB). Cell state lives
// redundantly in every lane's registers (post-reduction sums are uniform).
// ---------------------------------------------------------------------------
__global__ void __launch_bounds__(512) recur_coop(
    const float* __restrict__ Whh0,
    const float* __restrict__ Wih1, const float* __restrict__ Whh1,
    const float* __restrict__ bih1, const float* __restrict__ bhh1,
    const float* __restrict__ Wih2, const float* __restrict__ Whh2,
    const float* __restrict__ bih2, const float* __restrict__ bhh2)
{
    cg::grid_group grid = cg::this_grid();

    const int gw = blockIdx.x * 16 + (threadIdx.x >> 5);
    const int lane = threadIdx.x & 31;

    int role, j;
    if (gw < H0)            { role = 0; j = gw; }
    else if (gw < H0 + H1)  { role = 1; j = gw - H0; }
    else                    { role = 2; j = gw - H0 - H1; }

    // Preload biases (roles 1/2; role 0 biases are folded into g_xg0)
    float bsum[4] = {0.f, 0.f, 0.f, 0.f};
    if (role == 1) {
#pragma unroll
        for (int g = 0; g < 4; g++)
            bsum[g] = __ldg(bih1 + g * H1 + j) + __ldg(bhh1 + g * H1 + j);
    } else if (role == 2) {
#pragma unroll
        for (int g = 0; g < 4; g++)
            bsum[g] = __ldg(bih2 + g * H2 + j) + __ldg(bhh2 + g * H2 + j);
    }

    float c_state = 0.0f;

    for (int k = 0; k < NTICK; k++) {
        if (role == 0) {
            // -------- Layer 0: time t = k --------
            if (k < SEQ) {
                const float4* hp = (const float4*)(g_h0h + (size_t)k * H0);
                float4 h4[8];
#pragma unroll
                for (int m = 0; m < 8; m++) h4[m] = hp[m * 32 + lane];
                float a[4];
#pragma unroll
                for (int g = 0; g < 4; g++) {
                    const float4* wr = (const float4*)(Whh0 + (size_t)(g * H0 + j) * H0);
                    float s = 0.f;
#pragma unroll
                    for (int m = 0; m < 8; m++) {
                        float4 w4 = __ldg(wr + m * 32 + lane);
                        s += w4.x * h4[m].x + w4.y * h4[m].y + w4.z * h4[m].z + w4.w * h4[m].w;
                    }
                    a[g] = s;
                }
#pragma unroll
                for (int off = 16; off > 0; off >>= 1)
#pragma unroll
                    for (int g = 0; g < 4; g++)
                        a[g] += __shfl_xor_sync(0xffffffffu, a[g], off);
#pragma unroll
                for (int g = 0; g < 4; g++)
                    a[g] += __ldg(g_xg0 + (size_t)k * G0 + g * H0 + j);
                float ii = sigf(a[0]), ff = sigf(a[1]), gg = tanhf(a[2]), oo = sigf(a[3]);
                c_state = ff * c_state + ii * gg;
                float hval = oo * tanhf(c_state);
                if (lane == 0) g_h0h[(size_t)(k + 1) * H0 + j] = hval;
            }
        } else if (role == 1) {
            // -------- Layer 1: time t = k-1 --------
            if (k >= 1 && k <= SEQ) {
                const float4* h0p = (const float4*)(g_h0h + (size_t)k * H0);
                const float4* h1p = (const float4*)(g_h1h + (size_t)(k - 1) * H1);
                float4 hA[8], hB[4];
#pragma unroll
                for (int m = 0; m < 8; m++) hA[m] = h0p[m * 32 + lane];
#pragma unroll
                for (int m = 0; m < 4; m++) hB[m] = h1p[m * 32 + lane];
                float a[4];
#pragma unroll
                for (int g = 0; g < 4; g++) {
                    const float4* wi = (const float4*)(Wih1 + (size_t)(g * H1 + j) * H0);
                    const float4* wh = (const float4*)(Whh1 + (size_t)(g * H1 + j) * H1);
                    float s = 0.f;
#pragma unroll
                    for (int m = 0; m < 8; m++) {
                        float4 w4 = __ldg(wi + m * 32 + lane);
                        s += w4.x * hA[m].x + w4.y * hA[m].y + w4.z * hA[m].z + w4.w * hA[m].w;
                    }
#pragma unroll
                    for (int m = 0; m < 4; m++) {
                        float4 w4 = __ldg(wh + m * 32 + lane);
                        s += w4.x * hB[m].x + w4.y * hB[m].y + w4.z * hB[m].z + w4.w * hB[m].w;
                    }
                    a[g] = s;
                }
#pragma unroll
                for (int off = 16; off > 0; off >>= 1)
#pragma unroll
                    for (int g = 0; g < 4; g++)
                        a[g] += __shfl_xor_sync(0xffffffffu, a[g], off);
#pragma unroll
                for (int g = 0; g < 4; g++) a[g] += bsum[g];
                float ii = sigf(a[0]), ff = sigf(a[1]), gg = tanhf(a[2]), oo = sigf(a[3]);
                c_state = ff * c_state + ii * gg;
                float hval = oo * tanhf(c_state);
                if (lane == 0) g_h1h[(size_t)k * H1 + j] = hval;
            }
        } else {
            // -------- Layer 2: time t = k-2 --------
            if (k >= 2 && k <= SEQ + 1) {
                const float4* h1p = (const float4*)(g_h1h + (size_t)(k - 1) * H1);
                const float4* h2p = (const float4*)(g_h2h + (size_t)(k - 2) * H2);
                float4 hA[4], hB[2];
#pragma unroll
                for (int m = 0; m < 4; m++) hA[m] = h1p[m * 32 + lane];
#pragma unroll
                for (int m = 0; m < 2; m++) hB[m] = h2p[m * 32 + lane];
                float a[4];
#pragma unroll
                for (int g = 0; g < 4; g++) {
                    const float4* wi = (const float4*)(Wih2 + (size_t)(g * H2 + j) * H1);
                    const float4* wh = (const float4*)(Whh2 + (size_t)(g * H2 + j) * H2);
                    float s = 0.f;
#pragma unroll
                    for (int m = 0; m < 4; m++) {
                        float4 w4 = __ldg(wi + m * 32 + lane);
                        s += w4.x * hA[m].x + w4.y * hA[m].y + w4.z * hA[m].z + w4.w * hA[m].w;
                    }
#pragma unroll
                    for (int m = 0; m < 2; m++) {
                        float4 w4 = __ldg(wh + m * 32 + lane);
                        s += w4.x * hB[m].x + w4.y * hB[m].y + w4.z * hB[m].z + w4.w * hB[m].w;
                    }
                    a[g] = s;
                }
#pragma unroll
                for (int off = 16; off > 0; off >>= 1)
#pragma unroll
                    for (int g = 0; g < 4; g++)
                        a[g] += __shfl_xor_sync(0xffffffffu, a[g], off);
#pragma unroll
                for (int g = 0; g < 4; g++) a[g] += bsum[g];
                float ii = sigf(a[0]), ff = sigf(a[1]), gg = tanhf(a[2]), oo = sigf(a[3]);
                c_state = ff * c_state + ii * gg;
                float hval = oo * tanhf(c_state);
                if (lane == 0) g_h2h[(size_t)(k - 1) * H2 + j] = hval;
            }
        }
        grid.sync();
    }
}

// ---------------------------------------------------------------------------
// Kernel 3: out[t][o] = h2(t) . Wlin[o] + blin[o]   (1024 x 7 x 256)
// ---------------------------------------------------------------------------
__global__ void linout_kernel(const float* __restrict__ Wlin,
                              const float* __restrict__ blin,
                              float* __restrict__ out) {
    const int w = threadIdx.x >> 5, lane = threadIdx.x & 31;
    const int t = blockIdx.x * 4 + w;
    float hv[8];
#pragma unroll
    for (int m = 0; m < 8; m++) hv[m] = g_h2h[(size_t)(t + 1) * H2 + m * 32 + lane];
#pragma unroll
    for (int o = 0; o < OUTD; o++) {
        float acc = 0.f;
#pragma unroll
        for (int m = 0; m < 8; m++)
            acc += hv[m] * __ldg(Wlin + o * H2 + m * 32 + lane);
#pragma unroll
        for (int off = 16; off > 0; off >>= 1)
            acc += __shfl_xor_sync(0xffffffffu, acc, off);
        if (lane == 0) out[t * OUTD + o] = acc + __ldg(blin + o);
    }
}

// ---------------------------------------------------------------------------
extern "C" void kernel_launch(void* const* d_in, const int* in_sizes, int n_in,
                              void* d_out, int out_size) {
    const int*   tokens = (const int*)d_in[0];
    const float* emb  = (const float*)d_in[1];
    const float* Wih0 = (const float*)d_in[2];
    const float* Whh0 = (const float*)d_in[3];
    const float* bih0 = (const float*)d_in[4];
    const float* bhh0 = (const float*)d_in[5];
    const float* Wih1 = (const float*)d_in[6];
    const float* Whh1 = (const float*)d_in[7];
    const float* bih1 = (const float*)d_in[8];
    const float* bhh1 = (const float*)d_in[9];
    const float* Wih2 = (const float*)d_in[10];
    const float* Whh2 = (const float*)d_in[11];
    const float* bih2 = (const float*)d_in[12];
    const float* bhh2 = (const float*)d_in[13];
    const float* Wlin = (const float*)d_in[14];
    const float* blin = (const float*)d_in[15];
    float* out = (float*)d_out;

    xgemm_kernel<<<dim3(G0 / 64, SEQ / 64), 256>>>(tokens, emb, Wih0, bih0, bhh0);

    void* args[] = {
        (void*)&Whh0,
        (void*)&Wih1, (void*)&Whh1, (void*)&bih1, (void*)&bhh1,
        (void*)&Wih2, (void*)&Whh2, (void*)&bih2, (void*)&bhh2
    };
    cudaLaunchCooperativeKernel((void*)recur_coop,
                                dim3(TICK_CTAS), dim3(512), args, 0, (cudaStream_t)0);

    linout_kernel<<<SEQ / 4, 128>>>(Wlin, blin, out);
}

// round 8
// speedup vs baseline: 1.4615x; 1.4615x over previous
#include <cuda_runtime.h>
#include <cooperative_groups.h>
#include <math.h>

namespace cg = cooperative_groups;

// Problem constants
#define SEQ   1024
#define TB    64
#define EMBD  512
#define H0    1024
#define H1    512
#define H2    256
#define OUTD  7
#define G0    (4*H0)
#define NTICK (SEQ + 2)

// Persistent cooperative partition: one CTA per SM (smem-bound), 146 <= 148.
#define NCTA_L0 74
#define NCTA_L1 57
#define NCTA_L2 15
#define NCTA    (NCTA_L0 + NCTA_L1 + NCTA_L2)
#define EPC_L0  14   // elements per CTA, layer 0: 14*4*1024*4B = 229376 B smem
#define EPC_L1  9    // 9*4*1536*4B  = 221184 B
#define EPC_L2  18   // 18*4*768*4B  = 221184 B
#define SMEM_BYTES (EPC_L0 * 4 * H0 * 4)   // 229376 <= 232448 opt-in limit

// Scratch (static device arrays — no runtime allocation).
// h histories: slot (t+1) holds h(t); slot 0 holds the zero initial state and
// is NEVER written -> stays zero across graph replays. Write-once per replay.
__device__ __align__(16) float g_xg0[SEQ * G0];          // 16 MB: Wih0@x + bih0 + bhh0
__device__ __align__(16) float g_h0h[(SEQ + 1) * H0];
__device__ __align__(16) float g_h1h[(SEQ + 1) * H1];
__device__ __align__(16) float g_h2h[(SEQ + 1) * H2];

__device__ __forceinline__ float sigf(float x) { return 1.0f / (1.0f + expf(-x)); }

// ---------------------------------------------------------------------------
// Kernel 1: XG0[t][r] = sum_e emb[tok[t]][e] * Wih0[r][e] + bih0[r] + bhh0[r]
// 64x64 tile GEMM, fused embedding gather (only batch element 63 is live).
// ---------------------------------------------------------------------------
__global__ void xgemm_kernel(const int* __restrict__ tokens,
                             const float* __restrict__ emb,
                             const float* __restrict__ Wih0,
                             const float* __restrict__ bih0,
                             const float* __restrict__ bhh0) {
    __shared__ float As[64][33];
    __shared__ float Bs[64][33];
    __shared__ int toks[64];
    const int t0 = blockIdx.y * 64;
    const int r0 = blockIdx.x * 64;
    const int tid = threadIdx.x;
    if (tid < 64) toks[tid] = tokens[(t0 + tid) * TB + (TB - 1)];
    __syncthreads();

    float acc[4][4] = {};
    const int ty = tid >> 4, tx = tid & 15;

    for (int k0 = 0; k0 < EMBD; k0 += 32) {
#pragma unroll
        for (int l = 0; l < 2; l++) {
            int f4 = tid + l * 256;
            int row = f4 >> 3;
            int c4 = f4 & 7;
            float4 a = *(const float4*)(emb + (size_t)toks[row] * EMBD + k0 + c4 * 4);
            As[row][c4 * 4 + 0] = a.x; As[row][c4 * 4 + 1] = a.y;
            As[row][c4 * 4 + 2] = a.z; As[row][c4 * 4 + 3] = a.w;
            float4 b = *(const float4*)(Wih0 + (size_t)(r0 + row) * EMBD + k0 + c4 * 4);
            Bs[row][c4 * 4 + 0] = b.x; Bs[row][c4 * 4 + 1] = b.y;
            Bs[row][c4 * 4 + 2] = b.z; Bs[row][c4 * 4 + 3] = b.w;
        }
        __syncthreads();
#pragma unroll
        for (int kk = 0; kk < 32; kk++) {
            float a[4], b[4];
#pragma unroll
            for (int i = 0; i < 4; i++) a[i] = As[ty * 4 + i][kk];
#pragma unroll
            for (int j = 0; j < 4; j++) b[j] = Bs[tx * 4 + j][kk];
#pragma unroll
            for (int i = 0; i < 4; i++)
#pragma unroll
                for (int j = 0; j < 4; j++) acc[i][j] += a[i] * b[j];
        }
        __syncthreads();
    }
#pragma unroll
    for (int i = 0; i < 4; i++) {
#pragma unroll
        for (int j = 0; j < 4; j++) {
            int r = r0 + tx * 4 + j;
            int t = t0 + ty * 4 + i;
            g_xg0[(size_t)t * G0 + r] = acc[i][j] + bih0[r] + bhh0[r];
        }
    }
}

// ---------------------------------------------------------------------------
// Kernel 2: cooperative pipelined recurrence with SMEM-resident weights.
// Tick k: L0 computes t=k, L1 t=k-1, L2 t=k-2. ONE grid.sync() call site.
// One warp per hidden element (L2: two); weights staged once into smem.
// NOTE: biases are added AFTER the warp butterfly reduction (adding them to
// the per-lane accumulator multiplies them by 32 — the R2/R3/R7 bug).
// ---------------------------------------------------------------------------
__global__ void __launch_bounds__(512, 1) recur_coop(
    const float* __restrict__ Whh0,
    const float* __restrict__ Wih1, const float* __restrict__ Whh1,
    const float* __restrict__ bih1, const float* __restrict__ bhh1,
    const float* __restrict__ Wih2, const float* __restrict__ Whh2,
    const float* __restrict__ bih2, const float* __restrict__ bhh2)
{
    cg::grid_group grid = cg::this_grid();
    extern __shared__ float s_w[];

    const int b = blockIdx.x;
    const int tid = threadIdx.x;
    const int w = tid >> 5;
    const int lane = tid & 31;

    int role, base, count;
    if (b < NCTA_L0)                { role = 0; base = b * EPC_L0;              count = min(EPC_L0, H0 - base); }
    else if (b < NCTA_L0 + NCTA_L1) { role = 1; base = (b - NCTA_L0) * EPC_L1;  count = min(EPC_L1, H1 - base); }
    else                            { role = 2; base = (b - NCTA_L0 - NCTA_L1) * EPC_L2; count = min(EPC_L2, H2 - base); }

    // ---- Stage weights into smem (once) ----
    {
        float4* dst = (float4*)s_w;
        if (role == 0) {
            const int nf4 = count * 1024;            // slot: 4 gates x 256 f4
            for (int i = tid; i < nf4; i += 512) {
                int s = i >> 10, g = (i >> 8) & 3, c = i & 255;
                dst[i] = *((const float4*)(Whh0 + (size_t)(g * H0 + base + s) * H0) + c);
            }
        } else if (role == 1) {
            const int nf4 = count * 1536;            // slot: 4 gates x (256 ih + 128 hh) f4
            for (int i = tid; i < nf4; i += 512) {
                int s = i / 1536, rem = i - s * 1536;
                int g = rem / 384, q = rem - g * 384;
                int j = base + s;
                if (q < 256)
                    dst[i] = *((const float4*)(Wih1 + (size_t)(g * H1 + j) * H0) + q);
                else
                    dst[i] = *((const float4*)(Whh1 + (size_t)(g * H1 + j) * H1) + (q - 256));
            }
        } else {
            const int nf4 = count * 768;             // slot: 4 gates x (128 ih + 64 hh) f4
            for (int i = tid; i < nf4; i += 512) {
                int s = i / 768, rem = i - s * 768;
                int g = rem / 192, q = rem - g * 192;
                int j = base + s;
                if (q < 128)
                    dst[i] = *((const float4*)(Wih2 + (size_t)(g * H2 + j) * H1) + q);
                else
                    dst[i] = *((const float4*)(Whh2 + (size_t)(g * H2 + j) * H2) + (q - 128));
            }
        }
    }
    __syncthreads();

    // ---- Per-warp state ----
    const int j0 = base + w;                     // roles 0/1 element
    const bool act01 = (w < count);
    float c_state = 0.0f;                        // roles 0/1
    float bsum[4] = {0.f, 0.f, 0.f, 0.f};        // role 1 bias
    float c2[2] = {0.f, 0.f};                    // role 2 (two elements/warp)
    float bb2[2][4];

    if (role == 1 && act01) {
#pragma unroll
        for (int g = 0; g < 4; g++)
            bsum[g] = __ldg(bih1 + g * H1 + j0) + __ldg(bhh1 + g * H1 + j0);
    } else if (role == 2) {
#pragma unroll
        for (int ee = 0; ee < 2; ee++) {
            int e = w + ee * 16;
            if (e < count) {
                int j = base + e;
#pragma unroll
                for (int g = 0; g < 4; g++)
                    bb2[ee][g] = __ldg(bih2 + g * H2 + j) + __ldg(bhh2 + g * H2 + j);
            } else {
                bb2[ee][0] = bb2[ee][1] = bb2[ee][2] = bb2[ee][3] = 0.f;
            }
        }
    }

    for (int k = 0; k < NTICK; k++) {
        if (role == 0) {
            // -------- Layer 0: time t = k --------
            if (act01 && k < SEQ) {
                const float4* hp = (const float4*)(g_h0h + (size_t)k * H0);
                float4 h4[8];
#pragma unroll
                for (int m = 0; m < 8; m++) h4[m] = hp[m * 32 + lane];
                const float4* wb = (const float4*)s_w + (size_t)w * 1024;
                float a[4];
#pragma unroll
                for (int g = 0; g < 4; g++) {
                    const float4* wg = wb + g * 256;
                    float s = 0.f;
#pragma unroll
                    for (int m = 0; m < 8; m++) {
                        float4 w4 = wg[m * 32 + lane];
                        s += w4.x * h4[m].x + w4.y * h4[m].y + w4.z * h4[m].z + w4.w * h4[m].w;
                    }
                    a[g] = s;
                }
#pragma unroll
                for (int off = 16; off > 0; off >>= 1)
#pragma unroll
                    for (int g = 0; g < 4; g++)
                        a[g] += __shfl_xor_sync(0xffffffffu, a[g], off);
#pragma unroll
                for (int g = 0; g < 4; g++)
                    a[g] += __ldg(g_xg0 + (size_t)k * G0 + g * H0 + j0);
                float ii = sigf(a[0]), ff = sigf(a[1]), gg = tanhf(a[2]), oo = sigf(a[3]);
                c_state = ff * c_state + ii * gg;
                float hval = oo * tanhf(c_state);
                if (lane == 0) g_h0h[(size_t)(k + 1) * H0 + j0] = hval;
            }
        } else if (role == 1) {
            // -------- Layer 1: time t = k-1 --------
            if (act01 && k >= 1 && k <= SEQ) {
                const float4* h0p = (const float4*)(g_h0h + (size_t)k * H0);
                const float4* h1p = (const float4*)(g_h1h + (size_t)(k - 1) * H1);
                float4 hA[8], hB[4];
#pragma unroll
                for (int m = 0; m < 8; m++) hA[m] = h0p[m * 32 + lane];
#pragma unroll
                for (int m = 0; m < 4; m++) hB[m] = h1p[m * 32 + lane];
                const float4* wb = (const float4*)s_w + (size_t)w * 1536;
                float a[4];
#pragma unroll
                for (int g = 0; g < 4; g++) {
                    const float4* wi = wb + g * 384;
                    const float4* wh = wi + 256;
                    float s = 0.f;
#pragma unroll
                    for (int m = 0; m < 8; m++) {
                        float4 w4 = wi[m * 32 + lane];
                        s += w4.x * hA[m].x + w4.y * hA[m].y + w4.z * hA[m].z + w4.w * hA[m].w;
                    }
#pragma unroll
                    for (int m = 0; m < 4; m++) {
                        float4 w4 = wh[m * 32 + lane];
                        s += w4.x * hB[m].x + w4.y * hB[m].y + w4.z * hB[m].z + w4.w * hB[m].w;
                    }
                    a[g] = s;
                }
#pragma unroll
                for (int off = 16; off > 0; off >>= 1)
#pragma unroll
                    for (int g = 0; g < 4; g++)
                        a[g] += __shfl_xor_sync(0xffffffffu, a[g], off);
#pragma unroll
                for (int g = 0; g < 4; g++) a[g] += bsum[g];   // AFTER reduction
                float ii = sigf(a[0]), ff = sigf(a[1]), gg = tanhf(a[2]), oo = sigf(a[3]);
                c_state = ff * c_state + ii * gg;
                float hval = oo * tanhf(c_state);
                if (lane == 0) g_h1h[(size_t)k * H1 + j0] = hval;
            }
        } else {
            // -------- Layer 2: time t = k-2 (two elements per warp) --------
            if (k >= 2 && k <= SEQ + 1) {
                const float4* h1p = (const float4*)(g_h1h + (size_t)(k - 1) * H1);
                const float4* h2p = (const float4*)(g_h2h + (size_t)(k - 2) * H2);
                float4 hA[4], hB[2];
#pragma unroll
                for (int m = 0; m < 4; m++) hA[m] = h1p[m * 32 + lane];
#pragma unroll
                for (int m = 0; m < 2; m++) hB[m] = h2p[m * 32 + lane];
#pragma unroll
                for (int ee = 0; ee < 2; ee++) {
                    int e = w + ee * 16;
                    if (e < count) {
                        const float4* wb = (const float4*)s_w + (size_t)e * 768;
                        float a[4];
#pragma unroll
                        for (int g = 0; g < 4; g++) {
                            const float4* wi = wb + g * 192;
                            const float4* wh = wi + 128;
                            float s = 0.f;
#pragma unroll
                            for (int m = 0; m < 4; m++) {
                                float4 w4 = wi[m * 32 + lane];
                                s += w4.x * hA[m].x + w4.y * hA[m].y + w4.z * hA[m].z + w4.w * hA[m].w;
                            }
#pragma unroll
                            for (int m = 0; m < 2; m++) {
                                float4 w4 = wh[m * 32 + lane];
                                s += w4.x * hB[m].x + w4.y * hB[m].y + w4.z * hB[m].z + w4.w * hB[m].w;
                            }
                            a[g] = s;
                        }
#pragma unroll
                        for (int off = 16; off > 0; off >>= 1)
#pragma unroll
                            for (int g = 0; g < 4; g++)
                                a[g] += __shfl_xor_sync(0xffffffffu, a[g], off);
#pragma unroll
                        for (int g = 0; g < 4; g++) a[g] += bb2[ee][g];   // AFTER reduction
                        float ii = sigf(a[0]), ff = sigf(a[1]), gg = tanhf(a[2]), oo = sigf(a[3]);
                        c2[ee] = ff * c2[ee] + ii * gg;
                        float hval = oo * tanhf(c2[ee]);
                        if (lane == 0) g_h2h[(size_t)(k - 1) * H2 + base + e] = hval;
                    }
                }
            }
        }
        grid.sync();   // single call site for the whole grid
    }
}

// ---------------------------------------------------------------------------
// Kernel 3: out[t][o] = h2(t) . Wlin[o] + blin[o]   (1024 x 7 x 256)
// ---------------------------------------------------------------------------
__global__ void linout_kernel(const float* __restrict__ Wlin,
                              const float* __restrict__ blin,
                              float* __restrict__ out) {
    const int w = threadIdx.x >> 5, lane = threadIdx.x & 31;
    const int t = blockIdx.x * 4 + w;
    float hv[8];
#pragma unroll
    for (int m = 0; m < 8; m++) hv[m] = g_h2h[(size_t)(t + 1) * H2 + m * 32 + lane];
#pragma unroll
    for (int o = 0; o < OUTD; o++) {
        float acc = 0.f;
#pragma unroll
        for (int m = 0; m < 8; m++)
            acc += hv[m] * __ldg(Wlin + o * H2 + m * 32 + lane);
#pragma unroll
        for (int off = 16; off > 0; off >>= 1)
            acc += __shfl_xor_sync(0xffffffffu, acc, off);
        if (lane == 0) out[t * OUTD + o] = acc + __ldg(blin + o);
    }
}

// ---------------------------------------------------------------------------
extern "C" void kernel_launch(void* const* d_in, const int* in_sizes, int n_in,
                              void* d_out, int out_size) {
    const int*   tokens = (const int*)d_in[0];
    const float* emb  = (const float*)d_in[1];
    const float* Wih0 = (const float*)d_in[2];
    const float* Whh0 = (const float*)d_in[3];
    const float* bih0 = (const float*)d_in[4];
    const float* bhh0 = (const float*)d_in[5];
    const float* Wih1 = (const float*)d_in[6];
    const float* Whh1 = (const float*)d_in[7];
    const float* bih1 = (const float*)d_in[8];
    const float* bhh1 = (const float*)d_in[9];
    const float* Wih2 = (const float*)d_in[10];
    const float* Whh2 = (const float*)d_in[11];
    const float* bih2 = (const float*)d_in[12];
    const float* bhh2 = (const float*)d_in[13];
    const float* Wlin = (const float*)d_in[14];
    const float* blin = (const float*)d_in[15];
    float* out = (float*)d_out;

    cudaFuncSetAttribute(recur_coop, cudaFuncAttributeMaxDynamicSharedMemorySize, SMEM_BYTES);

    xgemm_kernel<<<dim3(G0 / 64, SEQ / 64), 256>>>(tokens, emb, Wih0, bih0, bhh0);

    const float* a0 = Whh0;
    const float* a1 = Wih1; const float* a2 = Whh1;
    const float* a3 = bih1; const float* a4 = bhh1;
    const float* a5 = Wih2; const float* a6 = Whh2;
    const float* a7 = bih2; const float* a8 = bhh2;
    void* args[] = { (void*)&a0, (void*)&a1, (void*)&a2, (void*)&a3, (void*)&a4,
                     (void*)&a5, (void*)&a6, (void*)&a7, (void*)&a8 };
    cudaLaunchCooperativeKernel((void*)recur_coop,
                                dim3(NCTA), dim3(512), args, SMEM_BYTES, (cudaStream_t)0);

    linout_kernel<<<SEQ / 4, 128>>>(Wlin, blin, out);
}